// round 13
// baseline (speedup 1.0000x reference)
#include <cuda_runtime.h>

// Problem dimensions (fixed by the reference)
#define TT_  4096   // sequence length T
#define EE_  256    // embed dim E
#define HH_  256    // per-direction hidden Hh
#define GG_  1024   // 4*Hh gate rows
#define KK_  32     // tags K
#define HC_  512    // concat hidden H

// ---------------- device scratch (no mallocs allowed) ----------------
__device__ float g_pre[2][TT_][GG_];   // input projections + biases, per direction (32 MB)
__device__ float g_h[TT_][HC_];        // concat hidden states (8 MB)
__device__ float g_feats[TT_][KK_];    // emission scores (512 KB)

// ---------------- packed fp32x2 helpers (SASS FFMA2) ----------------
__device__ __forceinline__ unsigned long long ffma2_(unsigned long long a,
                                                     unsigned long long b,
                                                     unsigned long long c) {
    unsigned long long d;
    asm("fma.rn.f32x2 %0, %1, %2, %3;" : "=l"(d) : "l"(a), "l"(b), "l"(c));
    return d;
}
__device__ __forceinline__ unsigned long long pack2_(float x) {
    unsigned long long d;
    asm("mov.b64 %0, {%1, %1};" : "=l"(d) : "f"(x));
    return d;
}
__device__ __forceinline__ float2 unpack2_(unsigned long long v) {
    float2 r;
    asm("mov.b64 {%0, %1}, %2;" : "=f"(r.x), "=f"(r.y) : "l"(v));
    return r;
}

// Dummy kernel: shifts ncu's launch index (-s 5) so the capture lands on
// lstm_rec_kernel instead of viterbi_kernel. Does no work.
__global__ void ncu_align_kernel() {}

// =====================================================================
// Phase 1: fused embedding gather + input projection GEMM (f32x2)
// =====================================================================
__global__ void __launch_bounds__(256) pre_gemm_kernel(
    const int* __restrict__ sent, const float* __restrict__ embed,
    const float* __restrict__ WihF, const float* __restrict__ bihF, const float* __restrict__ bhhF,
    const float* __restrict__ WihB, const float* __restrict__ bihB, const float* __restrict__ bhhB)
{
    const int dir = blockIdx.z;
    const float* __restrict__ Wih = dir ? WihB : WihF;
    const float* __restrict__ bih = dir ? bihB : bihF;
    const float* __restrict__ bhh = dir ? bhhB : bhhF;

    const int t0 = blockIdx.y * 64;
    const int j0 = blockIdx.x * 64;
    const int tid = threadIdx.x;

    __shared__ __align__(16) float As[32][68];
    __shared__ __align__(16) float Bs[32][68];
    __shared__ int ssent[64];

    if (tid < 64) ssent[tid] = sent[t0 + tid];
    __syncthreads();

    const int tl = tid >> 2;
    const int kq = (tid & 3) * 8;
    const int tm = tid & 15;
    const int tn = tid >> 4;

    unsigned long long acc2[4][2];
#pragma unroll
    for (int a = 0; a < 4; a++) { acc2[a][0] = 0ull; acc2[a][1] = 0ull; }

    for (int k0 = 0; k0 < EE_; k0 += 32) {
        const float4* ar = reinterpret_cast<const float4*>(embed + (size_t)ssent[tl] * EE_ + k0 + kq);
        float4 a0 = ar[0], a1 = ar[1];
        const float4* br = reinterpret_cast<const float4*>(Wih + (size_t)(j0 + tl) * EE_ + k0 + kq);
        float4 b0 = br[0], b1 = br[1];
        __syncthreads();
        As[kq + 0][tl] = a0.x; As[kq + 1][tl] = a0.y; As[kq + 2][tl] = a0.z; As[kq + 3][tl] = a0.w;
        As[kq + 4][tl] = a1.x; As[kq + 5][tl] = a1.y; As[kq + 6][tl] = a1.z; As[kq + 7][tl] = a1.w;
        Bs[kq + 0][tl] = b0.x; Bs[kq + 1][tl] = b0.y; Bs[kq + 2][tl] = b0.z; Bs[kq + 3][tl] = b0.w;
        Bs[kq + 4][tl] = b1.x; Bs[kq + 5][tl] = b1.y; Bs[kq + 6][tl] = b1.z; Bs[kq + 7][tl] = b1.w;
        __syncthreads();
#pragma unroll
        for (int kk = 0; kk < 32; kk++) {
            float4 av = *reinterpret_cast<const float4*>(&As[kk][tm * 4]);
            ulonglong2 bv = *reinterpret_cast<const ulonglong2*>(&Bs[kk][tn * 4]);
            unsigned long long sa0 = pack2_(av.x), sa1 = pack2_(av.y);
            unsigned long long sa2 = pack2_(av.z), sa3 = pack2_(av.w);
            acc2[0][0] = ffma2_(sa0, bv.x, acc2[0][0]); acc2[0][1] = ffma2_(sa0, bv.y, acc2[0][1]);
            acc2[1][0] = ffma2_(sa1, bv.x, acc2[1][0]); acc2[1][1] = ffma2_(sa1, bv.y, acc2[1][1]);
            acc2[2][0] = ffma2_(sa2, bv.x, acc2[2][0]); acc2[2][1] = ffma2_(sa2, bv.y, acc2[2][1]);
            acc2[3][0] = ffma2_(sa3, bv.x, acc2[3][0]); acc2[3][1] = ffma2_(sa3, bv.y, acc2[3][1]);
        }
    }

    float bias[4];
#pragma unroll
    for (int b = 0; b < 4; b++) bias[b] = bih[j0 + tn * 4 + b] + bhh[j0 + tn * 4 + b];

#pragma unroll
    for (int a = 0; a < 4; a++) {
        float2 p0 = unpack2_(acc2[a][0]);
        float2 p1 = unpack2_(acc2[a][1]);
        float4 v;
        v.x = p0.x + bias[0]; v.y = p0.y + bias[1];
        v.z = p1.x + bias[2]; v.w = p1.y + bias[3];
        *reinterpret_cast<float4*>(&g_pre[dir][t0 + tm * 4 + a][j0 + tn * 4]) = v;
    }
}

// ---------------- recurrence helpers ----------------
__device__ __forceinline__ float sigm_(float x) {
    return __fdividef(1.f, 1.f + __expf(-x));     // rcp.approx path
}
__device__ __forceinline__ float tanh_(float x) {
    return __fdividef(2.f, 1.f + __expf(-2.f * x)) - 1.f;
}
__device__ __forceinline__ void cluster_sync_() {
    asm volatile("barrier.cluster.arrive.aligned;" ::: "memory");
    asm volatile("barrier.cluster.wait.aligned;" ::: "memory");
}
__device__ __forceinline__ void mbar_wait_(unsigned mbar, unsigned parity) {
    unsigned done;
    asm volatile(
        "{\n\t.reg .pred p;\n\t"
        "mbarrier.try_wait.parity.acquire.cta.shared::cta.b64 p, [%1], %2, 0x989680;\n\t"
        "selp.b32 %0, 1, 0, p;\n\t}"
        : "=r"(done) : "r"(mbar), "r"(parity) : "memory");
    while (!done) {
        asm volatile(
            "{\n\t.reg .pred p;\n\t"
            "mbarrier.try_wait.parity.acquire.cta.shared::cta.b64 p, [%1], %2, 0x989680;\n\t"
            "selp.b32 %0, 1, 0, p;\n\t}"
            : "=r"(done) : "r"(mbar), "r"(parity) : "memory");
    }
}

// =====================================================================
// Phase 2: BiLSTM recurrence. 2 clusters of 8 CTAs, 512 threads/CTA.
// tid = u*16 + sub16, sub16 = g*4 + q. Each thread owns a QUARTER row
// (64 weights in regs): halves the per-warp latency chain and doubles
// occupancy (4 warps/SMSP) vs the 256-thread version — the ncu profile
// showed occ=12.5%, issue=18% (pure latency-bound).
// Quarter-sum via shfl_xor(1,2); gate butterfly via shfl_xor(4,8,12).
// Sends: threads with sub16<8 send to dest CTA sub16 (hoisted mapa) +
// remote arrive; barrier count 256/phase (unchanged from proven R7).
// =====================================================================
__global__ void __cluster_dims__(8, 1, 1) __launch_bounds__(512, 1) lstm_rec_kernel(
    const float* __restrict__ WhhF, const float* __restrict__ WhhB,
    const float* __restrict__ h0, const float* __restrict__ c0)
{
    __shared__ __align__(16) float hbuf[2][HH_];     // assembled h (all 8 chunks)
    __shared__ __align__(8) unsigned long long mbar[2];

    unsigned rank;
    asm("mov.u32 %0, %%cluster_ctarank;" : "=r"(rank));
    const int dir = blockIdx.x >> 3;
    const float* __restrict__ Whh = dir ? WhhB : WhhF;
    const float* __restrict__ pre = &g_pre[dir][0][0];

    const int tid   = threadIdx.x;
    const int u     = tid >> 4;         // hidden unit 0..31 within CTA
    const int sub16 = tid & 15;
    const int g     = sub16 >> 2;       // gate 0..3 (i,f,g,o)
    const int q     = sub16 & 3;        // quarter of the 256-wide row
    const int gu    = (int)rank * 32 + u;
    const int grow  = g * HH_ + gu;
    const bool sender = (sub16 < 8);    // dest CTA = sub16

    // quarter-row weights into registers as packed f32x2 (16 chunks of 16B)
    unsigned long long w2[32];
    {
        const ulonglong2* wr = reinterpret_cast<const ulonglong2*>(
            Whh + (size_t)grow * HH_ + q * 64);
#pragma unroll
        for (int k = 0; k < 16; k++) {
            ulonglong2 v = wr[k];
            w2[2 * k] = v.x; w2[2 * k + 1] = v.y;
        }
    }

    // init state (all 16 threads of a unit track c redundantly & identically)
    if (tid < HH_) hbuf[0][tid] = h0[dir * HH_ + tid];
    float c = c0[dir * HH_ + gu];

    unsigned mbl[2];
    mbl[0] = (unsigned)__cvta_generic_to_shared(&mbar[0]);
    mbl[1] = (unsigned)__cvta_generic_to_shared(&mbar[1]);

    // hoisted remote addresses: this thread's destination slot in CTA 'sub16'
    unsigned dstR[2], mbaR[2];
    {
        unsigned dd = sender ? (unsigned)sub16 : 0u;
        unsigned h0a = (unsigned)__cvta_generic_to_shared(&hbuf[0][0]) + ((unsigned)gu << 2);
        unsigned h1a = (unsigned)__cvta_generic_to_shared(&hbuf[1][0]) + ((unsigned)gu << 2);
        asm("mapa.shared::cluster.u32 %0, %1, %2;" : "=r"(dstR[0]) : "r"(h0a), "r"(dd));
        asm("mapa.shared::cluster.u32 %0, %1, %2;" : "=r"(dstR[1]) : "r"(h1a), "r"(dd));
        asm("mapa.shared::cluster.u32 %0, %1, %2;" : "=r"(mbaR[0]) : "r"(mbl[0]), "r"(dd));
        asm("mapa.shared::cluster.u32 %0, %1, %2;" : "=r"(mbaR[1]) : "r"(mbl[1]), "r"(dd));
    }

    if (tid == 0) {
        // 256 arrives per phase: 32 units x 8 source CTAs
        asm volatile("mbarrier.init.shared.b64 [%0], %1;" :: "r"(mbl[0]), "r"(256u) : "memory");
        asm volatile("mbarrier.init.shared.b64 [%0], %1;" :: "r"(mbl[1]), "r"(256u) : "memory");
    }
    __syncthreads();
    cluster_sync_();   // mbarrier init + hbuf[0] visible cluster-wide

    int phase0 = 0, phase1 = 0;
    const float gmul = (g == 2) ? 2.f : 1.f;   // tanh(x) = 2*sigm(2x)-1
    const int b0 = g & 1, b1 = g >> 1;

    // software prefetch of the input projection, 1 step ahead
    float prevN = pre[(size_t)(dir ? (TT_ - 1) : 0) * GG_ + grow];

    for (int s = 0; s < TT_; s++) {
        const int tt = dir ? (TT_ - 1 - s) : s;

        const float prev = prevN;
        if (s + 1 < TT_) {
            const int tn2 = dir ? (TT_ - 2 - s) : (s + 1);
            prevN = pre[(size_t)tn2 * GG_ + grow];   // issued early, consumed next step
        }

        const ulonglong2* h2 = reinterpret_cast<const ulonglong2*>(&hbuf[s & 1][q << 6]);
        unsigned long long a0 = 0ull, a1 = 0ull;
#pragma unroll
        for (int k = 0; k < 16; k++) {
            ulonglong2 hv = h2[k];
            a0 = ffma2_(w2[2 * k],     hv.x, a0);
            a1 = ffma2_(w2[2 * k + 1], hv.y, a1);
        }
        float2 p0 = unpack2_(a0), p1 = unpack2_(a1);
        float val = (p0.x + p0.y) + (p1.x + p1.y);
        if (q == 0) val += prev;
        val += __shfl_xor_sync(0xffffffffu, val, 1);
        val += __shfl_xor_sync(0xffffffffu, val, 2);   // full pre-activation (all quarters)

        // own-gate nonlinearity
        float sg = sigm_(val * gmul);
        float A = (g == 2) ? (2.f * sg - 1.f) : sg;    // act of gate g

        // butterfly exchange over gate bits (bits 2,3 of sub16), parallel from A
        float B = __shfl_xor_sync(0xffffffffu, A, 4);  // gate g^1
        float C = __shfl_xor_sync(0xffffffffu, A, 8);  // gate g^2
        float D = __shfl_xor_sync(0xffffffffu, A, 12); // gate g^3
        // gate j = arr[j ^ g], arr = {A,B,C,D}
        float gi = b1 ? (b0 ? D : C) : (b0 ? B : A);   // gate 0 (i)
        float gf = b1 ? (b0 ? C : D) : (b0 ? A : B);   // gate 1 (f)
        float gg = b1 ? (b0 ? B : A) : (b0 ? D : C);   // gate 2 (g)
        float go = b1 ? (b0 ? A : B) : (b0 ? C : D);   // gate 3 (o)

        c = gf * c + gi * gg;
        float h = go * tanh_(c);

        if (s + 1 < TT_) {
            const int nb = (s + 1) & 1;
            if (sender) {
                // one remote store + one remote arrive per sender (dest = sub16)
                asm volatile("st.shared::cluster.f32 [%0], %1;"
                             :: "r"(dstR[nb]), "f"(h) : "memory");
                asm volatile("mbarrier.arrive.shared::cluster.b64 _, [%0];"
                             :: "r"(mbaR[nb]) : "memory");
            }
        }

        if (sub16 == 0) g_h[tt][dir * HH_ + gu] = h;   // off critical path

        if (s + 1 < TT_) {
            if ((s + 1) & 1) { mbar_wait_(mbl[1], (unsigned)(phase1 & 1)); phase1++; }
            else             { mbar_wait_(mbl[0], (unsigned)(phase0 & 1)); phase0++; }
        }
    }
    cluster_sync_();   // safe teardown
}

// =====================================================================
// Phase 3: feats[t][j] = h[t] . W_out[j] + b_out[j]   (32 t-rows/block)
// =====================================================================
__global__ void __launch_bounds__(256) feats_kernel(
    const float* __restrict__ Wout, const float* __restrict__ bout)
{
    extern __shared__ float sm[];
    float* Ws = sm;                 // [32][513] padded
    float* hs = sm + KK_ * 513;     // [32][512]
    const int t0 = blockIdx.x * 32;
    const int tid = threadIdx.x;

    for (int i = tid; i < KK_ * HC_; i += 256) {
        int j = i >> 9, k = i & 511;
        Ws[j * 513 + k] = Wout[i];
    }
    const float* hflat = &g_h[t0][0];
    for (int i = tid; i < 32 * HC_; i += 256) hs[i] = hflat[i];
    __syncthreads();

    const int j = tid & 31;
    const int r0 = tid >> 5;
    const float bj = bout[j];
    for (int r = r0; r < 32; r += 8) {
        const float* hr = hs + r * HC_;
        const float* wr = Ws + j * 513;
        float s0 = 0.f, s1 = 0.f, s2 = 0.f, s3 = 0.f;
#pragma unroll 4
        for (int k = 0; k < HC_; k += 4) {
            s0 = fmaf(hr[k + 0], wr[k + 0], s0);
            s1 = fmaf(hr[k + 1], wr[k + 1], s1);
            s2 = fmaf(hr[k + 2], wr[k + 2], s2);
            s3 = fmaf(hr[k + 3], wr[k + 3], s3);
        }
        g_feats[t0 + r][j] = (s0 + s1) + (s2 + s3) + bj;
    }
}

// =====================================================================
// Phase 4: Viterbi. One block, 1024 threads: warp = tag j, lane = prev tag i.
// =====================================================================
#define VCHUNK 256

__global__ void __launch_bounds__(1024) viterbi_kernel(
    const float* __restrict__ trans, float* __restrict__ out, int out_size)
{
    extern __shared__ float smv[];
    float* transS = smv;                         // [32][32] transS[j][i] = trans[i][j]
    float* alpha  = transS + 1024;               // [2][32]
    float* fbuf   = alpha + 64;                  // [VCHUNK][32]
    unsigned char* ixs = (unsigned char*)(fbuf + VCHUNK * 32);  // [T-1][32]

    const int tid = threadIdx.x;
    const int i = tid & 31;     // previous tag (lane)
    const int j = tid >> 5;     // current tag (warp)

    transS[j * 32 + i] = trans[i * 32 + j];
    if (tid < 32) alpha[tid] = g_feats[0][tid];
    __syncthreads();
    const float tr = transS[j * 32 + i];
    const float* fflat = &g_feats[0][0];

    int p = 0;
    for (int t = 1; t < TT_; t++) {
        const int ci = (t - 1) & (VCHUNK - 1);
        if (ci == 0) {
            __syncthreads();
            const int base2 = t * 32;
            for (int u = tid; u < VCHUNK * 32 && base2 + u < TT_ * 32; u += 1024)
                fbuf[u] = fflat[base2 + u];
            __syncthreads();
        }
        float s = alpha[p * 32 + i] + tr;
        unsigned uu = __float_as_uint(s);
        uu = (uu & 0x80000000u) ? ~uu : (uu | 0x80000000u);
        unsigned best = __reduce_max_sync(0xffffffffu, uu);
        unsigned m = __ballot_sync(0xffffffffu, uu == best);
        int arg = __ffs(m) - 1;                     // lowest index on ties (matches argmax)
        float bs = __shfl_sync(0xffffffffu, s, arg);
        if (i == 0) {
            alpha[(p ^ 1) * 32 + j] = bs + fbuf[ci * 32 + j];
            ixs[(t - 1) * 32 + j] = (unsigned char)arg;
        }
        __syncthreads();
        p ^= 1;
    }

    if (tid < 32) {
        float s = alpha[p * 32 + i];
        unsigned uu = __float_as_uint(s);
        uu = (uu & 0x80000000u) ? ~uu : (uu | 0x80000000u);
        unsigned best = __reduce_max_sync(0xffffffffu, uu);
        unsigned m = __ballot_sync(0xffffffffu, uu == best);
        int arg = __ffs(m) - 1;
        float score = __shfl_sync(0xffffffffu, s, arg);
        if (i == 0) {
            if (out_size > TT_) out[TT_] = score;
            int cur = arg;
            out[TT_ - 1] = (float)cur;
            for (int t = TT_ - 2; t >= 0; t--) {
                cur = ixs[t * 32 + cur];
                out[t] = (float)cur;
            }
        }
    }
}

// =====================================================================
extern "C" void kernel_launch(void* const* d_in, const int* in_sizes, int n_in,
                              void* d_out, int out_size)
{
    const int*   sent  = (const int*)  d_in[0];
    const float* embed = (const float*)d_in[1];
    const float* WihF  = (const float*)d_in[2];
    const float* WhhF  = (const float*)d_in[3];
    const float* bihF  = (const float*)d_in[4];
    const float* bhhF  = (const float*)d_in[5];
    const float* WihB  = (const float*)d_in[6];
    const float* WhhB  = (const float*)d_in[7];
    const float* bihB  = (const float*)d_in[8];
    const float* bhhB  = (const float*)d_in[9];
    const float* h0    = (const float*)d_in[10];
    const float* c0    = (const float*)d_in[11];
    const float* Wout  = (const float*)d_in[12];
    const float* bout  = (const float*)d_in[13];
    const float* trans = (const float*)d_in[14];
    float* out = (float*)d_out;

    const int feats_smem = (KK_ * 513 + 32 * HC_) * 4;                        // ~131 KB
    const int vit_smem   = (1024 + 64 + VCHUNK * 32) * 4 + (TT_ - 1) * 32;    // ~168 KB
    cudaFuncSetAttribute(feats_kernel,   cudaFuncAttributeMaxDynamicSharedMemorySize, feats_smem);
    cudaFuncSetAttribute(viterbi_kernel, cudaFuncAttributeMaxDynamicSharedMemorySize, vit_smem);

    pre_gemm_kernel<<<dim3(16, 64, 2), 256>>>(sent, embed, WihF, bihF, bhhF, WihB, bihB, bhhB);
    // ncu alignment: shift -s 5 capture onto lstm_rec_kernel (launch idx 5)
    ncu_align_kernel<<<1, 32>>>();
    ncu_align_kernel<<<1, 32>>>();
    lstm_rec_kernel<<<16, 512>>>(WhhF, WhhB, h0, c0);
    feats_kernel<<<128, 256, feats_smem>>>(Wout, bout);
    viterbi_kernel<<<1, 1024, vit_smem>>>(trans, out, out_size);
}

// round 14
// speedup vs baseline: 1.8179x; 1.8179x over previous
#include <cuda_runtime.h>

// Problem dimensions (fixed by the reference)
#define TT_  4096   // sequence length T
#define EE_  256    // embed dim E
#define HH_  256    // per-direction hidden Hh
#define GG_  1024   // 4*Hh gate rows
#define KK_  32     // tags K
#define HC_  512    // concat hidden H

// hbuf padded row: halves at float 0 and float 144 (byte 576 -> disjoint banks)
#define HPAD_ 288

// ---------------- device scratch (no mallocs allowed) ----------------
__device__ float g_pre[2][TT_][GG_];   // input projections + biases, per direction (32 MB)
__device__ float g_h[TT_][HC_];        // concat hidden states (8 MB)
__device__ float g_feats[TT_][KK_];    // emission scores (512 KB)

// ---------------- packed fp32x2 helpers (SASS FFMA2) ----------------
__device__ __forceinline__ unsigned long long ffma2_(unsigned long long a,
                                                     unsigned long long b,
                                                     unsigned long long c) {
    unsigned long long d;
    asm("fma.rn.f32x2 %0, %1, %2, %3;" : "=l"(d) : "l"(a), "l"(b), "l"(c));
    return d;
}
__device__ __forceinline__ unsigned long long pack2_(float x) {
    unsigned long long d;
    asm("mov.b64 %0, {%1, %1};" : "=l"(d) : "f"(x));
    return d;
}
__device__ __forceinline__ float2 unpack2_(unsigned long long v) {
    float2 r;
    asm("mov.b64 {%0, %1}, %2;" : "=f"(r.x), "=f"(r.y) : "l"(v));
    return r;
}

// Dummy kernel: shifts ncu's launch index (-s 5) so the capture lands on
// lstm_rec_kernel. Does no work.
__global__ void ncu_align_kernel() {}

// =====================================================================
// Phase 1: fused embedding gather + input projection GEMM (f32x2)
// =====================================================================
__global__ void __launch_bounds__(256) pre_gemm_kernel(
    const int* __restrict__ sent, const float* __restrict__ embed,
    const float* __restrict__ WihF, const float* __restrict__ bihF, const float* __restrict__ bhhF,
    const float* __restrict__ WihB, const float* __restrict__ bihB, const float* __restrict__ bhhB)
{
    const int dir = blockIdx.z;
    const float* __restrict__ Wih = dir ? WihB : WihF;
    const float* __restrict__ bih = dir ? bihB : bihF;
    const float* __restrict__ bhh = dir ? bhhB : bhhF;

    const int t0 = blockIdx.y * 64;
    const int j0 = blockIdx.x * 64;
    const int tid = threadIdx.x;

    __shared__ __align__(16) float As[32][68];
    __shared__ __align__(16) float Bs[32][68];
    __shared__ int ssent[64];

    if (tid < 64) ssent[tid] = sent[t0 + tid];
    __syncthreads();

    const int tl = tid >> 2;
    const int kq = (tid & 3) * 8;
    const int tm = tid & 15;
    const int tn = tid >> 4;

    unsigned long long acc2[4][2];
#pragma unroll
    for (int a = 0; a < 4; a++) { acc2[a][0] = 0ull; acc2[a][1] = 0ull; }

    for (int k0 = 0; k0 < EE_; k0 += 32) {
        const float4* ar = reinterpret_cast<const float4*>(embed + (size_t)ssent[tl] * EE_ + k0 + kq);
        float4 a0 = ar[0], a1 = ar[1];
        const float4* br = reinterpret_cast<const float4*>(Wih + (size_t)(j0 + tl) * EE_ + k0 + kq);
        float4 b0 = br[0], b1 = br[1];
        __syncthreads();
        As[kq + 0][tl] = a0.x; As[kq + 1][tl] = a0.y; As[kq + 2][tl] = a0.z; As[kq + 3][tl] = a0.w;
        As[kq + 4][tl] = a1.x; As[kq + 5][tl] = a1.y; As[kq + 6][tl] = a1.z; As[kq + 7][tl] = a1.w;
        Bs[kq + 0][tl] = b0.x; Bs[kq + 1][tl] = b0.y; Bs[kq + 2][tl] = b0.z; Bs[kq + 3][tl] = b0.w;
        Bs[kq + 4][tl] = b1.x; Bs[kq + 5][tl] = b1.y; Bs[kq + 6][tl] = b1.z; Bs[kq + 7][tl] = b1.w;
        __syncthreads();
#pragma unroll
        for (int kk = 0; kk < 32; kk++) {
            float4 av = *reinterpret_cast<const float4*>(&As[kk][tm * 4]);
            ulonglong2 bv = *reinterpret_cast<const ulonglong2*>(&Bs[kk][tn * 4]);
            unsigned long long sa0 = pack2_(av.x), sa1 = pack2_(av.y);
            unsigned long long sa2 = pack2_(av.z), sa3 = pack2_(av.w);
            acc2[0][0] = ffma2_(sa0, bv.x, acc2[0][0]); acc2[0][1] = ffma2_(sa0, bv.y, acc2[0][1]);
            acc2[1][0] = ffma2_(sa1, bv.x, acc2[1][0]); acc2[1][1] = ffma2_(sa1, bv.y, acc2[1][1]);
            acc2[2][0] = ffma2_(sa2, bv.x, acc2[2][0]); acc2[2][1] = ffma2_(sa2, bv.y, acc2[2][1]);
            acc2[3][0] = ffma2_(sa3, bv.x, acc2[3][0]); acc2[3][1] = ffma2_(sa3, bv.y, acc2[3][1]);
        }
    }

    float bias[4];
#pragma unroll
    for (int b = 0; b < 4; b++) bias[b] = bih[j0 + tn * 4 + b] + bhh[j0 + tn * 4 + b];

#pragma unroll
    for (int a = 0; a < 4; a++) {
        float2 p0 = unpack2_(acc2[a][0]);
        float2 p1 = unpack2_(acc2[a][1]);
        float4 v;
        v.x = p0.x + bias[0]; v.y = p0.y + bias[1];
        v.z = p1.x + bias[2]; v.w = p1.y + bias[3];
        *reinterpret_cast<float4*>(&g_pre[dir][t0 + tm * 4 + a][j0 + tn * 4]) = v;
    }
}

// ---------------- recurrence helpers ----------------
__device__ __forceinline__ float sigm_(float x) {
    return __fdividef(1.f, 1.f + __expf(-x));     // rcp.approx path
}
__device__ __forceinline__ float tanh_(float x) {
    return __fdividef(2.f, 1.f + __expf(-2.f * x)) - 1.f;
}
__device__ __forceinline__ void cluster_sync_() {
    asm volatile("barrier.cluster.arrive.aligned;" ::: "memory");
    asm volatile("barrier.cluster.wait.aligned;" ::: "memory");
}
__device__ __forceinline__ void mbar_wait_(unsigned mbar, unsigned parity) {
    unsigned done;
    asm volatile(
        "{\n\t.reg .pred p;\n\t"
        "mbarrier.try_wait.parity.acquire.cta.shared::cta.b64 p, [%1], %2, 0x989680;\n\t"
        "selp.b32 %0, 1, 0, p;\n\t}"
        : "=r"(done) : "r"(mbar), "r"(parity) : "memory");
    while (!done) {
        asm volatile(
            "{\n\t.reg .pred p;\n\t"
            "mbarrier.try_wait.parity.acquire.cta.shared::cta.b64 p, [%1], %2, 0x989680;\n\t"
            "selp.b32 %0, 1, 0, p;\n\t}"
            : "=r"(done) : "r"(mbar), "r"(parity) : "memory");
    }
}

// =====================================================================
// Phase 2: BiLSTM recurrence (R10 structure, 256 thr/CTA). 2 clusters x 8.
// tid = u*8 + sub, sub = g*2 + half. Per-thread single-destination send,
// hoisted mapa, acquire.cta waits.
// NEW: hbuf rows padded to 288 floats (halves at 0 / 144) -> the two
// LDS.128 address streams hit DISJOINT bank groups (was 2-way conflict);
// dot uses 4 accumulator chains; butterfly fully parallel from A.
// =====================================================================
__global__ void __cluster_dims__(8, 1, 1) __launch_bounds__(256, 1) lstm_rec_kernel(
    const float* __restrict__ WhhF, const float* __restrict__ WhhB,
    const float* __restrict__ h0, const float* __restrict__ c0)
{
    __shared__ __align__(16) float hbuf[2][HPAD_];   // halves at [0..127], [144..271]
    __shared__ __align__(8) unsigned long long mbar[2];

    unsigned rank;
    asm("mov.u32 %0, %%cluster_ctarank;" : "=r"(rank));
    const int dir = blockIdx.x >> 3;
    const float* __restrict__ Whh = dir ? WhhB : WhhF;
    const float* __restrict__ pre = &g_pre[dir][0][0];

    const int tid  = threadIdx.x;
    const int u    = tid >> 3;          // hidden unit 0..31 within CTA
    const int sub  = tid & 7;           // also: destination CTA for the send
    const int g    = sub >> 1;          // gate 0..3 (i,f,g,o)
    const int half = sub & 1;           // column half
    const int gu   = (int)rank * 32 + u;
    const int grow = g * HH_ + gu;
    // padded slot index for value gu: halves split at 128 with 16-float gap
    const int gup  = gu + ((gu >> 7) << 4);

    // weights into registers as packed f32x2
    unsigned long long w2[64];
    {
        const ulonglong2* wr = reinterpret_cast<const ulonglong2*>(
            Whh + (size_t)grow * HH_ + half * 128);
#pragma unroll
        for (int k = 0; k < 32; k++) {
            ulonglong2 v = wr[k];
            w2[2 * k] = v.x; w2[2 * k + 1] = v.y;
        }
    }

    // init state (all 8 threads of a unit track c redundantly & identically)
    if (tid < HH_) hbuf[0][tid + ((tid >> 7) << 4)] = h0[dir * HH_ + tid];
    float c = c0[dir * HH_ + gu];

    unsigned mbl[2];
    mbl[0] = (unsigned)__cvta_generic_to_shared(&mbar[0]);
    mbl[1] = (unsigned)__cvta_generic_to_shared(&mbar[1]);

    // hoisted remote addresses: this thread's destination slot in CTA 'sub'
    unsigned dstR[2], mbaR[2];
    {
        unsigned h0a = (unsigned)__cvta_generic_to_shared(&hbuf[0][0]) + ((unsigned)gup << 2);
        unsigned h1a = (unsigned)__cvta_generic_to_shared(&hbuf[1][0]) + ((unsigned)gup << 2);
        asm("mapa.shared::cluster.u32 %0, %1, %2;" : "=r"(dstR[0]) : "r"(h0a), "r"((unsigned)sub));
        asm("mapa.shared::cluster.u32 %0, %1, %2;" : "=r"(dstR[1]) : "r"(h1a), "r"((unsigned)sub));
        asm("mapa.shared::cluster.u32 %0, %1, %2;" : "=r"(mbaR[0]) : "r"(mbl[0]), "r"((unsigned)sub));
        asm("mapa.shared::cluster.u32 %0, %1, %2;" : "=r"(mbaR[1]) : "r"(mbl[1]), "r"((unsigned)sub));
    }

    if (tid == 0) {
        // 256 arrives per phase: 32 units x 8 source CTAs
        asm volatile("mbarrier.init.shared.b64 [%0], %1;" :: "r"(mbl[0]), "r"(256u) : "memory");
        asm volatile("mbarrier.init.shared.b64 [%0], %1;" :: "r"(mbl[1]), "r"(256u) : "memory");
    }
    __syncthreads();
    cluster_sync_();   // mbarrier init + hbuf[0] visible cluster-wide

    int phase0 = 0, phase1 = 0;
    const float gmul = (g == 2) ? 2.f : 1.f;   // tanh(x) = 2*sigm(2x)-1
    const int b0 = g & 1, b1 = g >> 1;

    // software prefetch of the input projection, 1 step ahead
    float prevN = pre[(size_t)(dir ? (TT_ - 1) : 0) * GG_ + grow];

    for (int s = 0; s < TT_; s++) {
        const int tt = dir ? (TT_ - 1 - s) : s;

        const float prev = prevN;
        if (s + 1 < TT_) {
            const int tn2 = dir ? (TT_ - 2 - s) : (s + 1);
            prevN = pre[(size_t)tn2 * GG_ + grow];   // issued early, consumed next step
        }

        // conflict-free: half-0 at float 0, half-1 at float 144 (bank-disjoint)
        const ulonglong2* h2 = reinterpret_cast<const ulonglong2*>(&hbuf[s & 1][half * 144]);
        unsigned long long a0 = 0ull, a1 = 0ull, a2 = 0ull, a3 = 0ull;
#pragma unroll
        for (int k = 0; k < 32; k += 2) {
            ulonglong2 hv0 = h2[k];
            ulonglong2 hv1 = h2[k + 1];
            a0 = ffma2_(w2[2 * k],     hv0.x, a0);
            a1 = ffma2_(w2[2 * k + 1], hv0.y, a1);
            a2 = ffma2_(w2[2 * k + 2], hv1.x, a2);
            a3 = ffma2_(w2[2 * k + 3], hv1.y, a3);
        }
        float2 p0 = unpack2_(a0), p1 = unpack2_(a1);
        float2 p2 = unpack2_(a2), p3 = unpack2_(a3);
        float val = ((p0.x + p0.y) + (p1.x + p1.y)) + ((p2.x + p2.y) + (p3.x + p3.y));
        if (!half) val += prev;
        val += __shfl_xor_sync(0xffffffffu, val, 1);   // full gate pre-activation (both halves)

        // own-gate nonlinearity
        float sg = sigm_(val * gmul);
        float A = (g == 2) ? (2.f * sg - 1.f) : sg;    // act of gate g

        // butterfly exchange: all three peers fetched in PARALLEL from A
        float B = __shfl_xor_sync(0xffffffffu, A, 2);  // gate g^1
        float C = __shfl_xor_sync(0xffffffffu, A, 4);  // gate g^2
        float D = __shfl_xor_sync(0xffffffffu, A, 6);  // gate g^3
        // gate j = arr[j ^ g], arr = {A,B,C,D}
        float gi = b1 ? (b0 ? D : C) : (b0 ? B : A);   // gate 0 (i)
        float gf = b1 ? (b0 ? C : D) : (b0 ? A : B);   // gate 1 (f)
        float gg = b1 ? (b0 ? B : A) : (b0 ? D : C);   // gate 2 (g)
        float go = b1 ? (b0 ? A : B) : (b0 ? C : D);   // gate 3 (o)

        c = gf * c + gi * gg;
        float h = go * tanh_(c);

        if (s + 1 < TT_) {
            const int nb = (s + 1) & 1;
            // one remote store + one remote arrive per thread (dest = sub)
            asm volatile("st.shared::cluster.f32 [%0], %1;"
                         :: "r"(dstR[nb]), "f"(h) : "memory");
            asm volatile("mbarrier.arrive.shared::cluster.b64 _, [%0];"
                         :: "r"(mbaR[nb]) : "memory");
        }

        if (sub == 0) g_h[tt][dir * HH_ + gu] = h;   // off critical path

        if (s + 1 < TT_) {
            if ((s + 1) & 1) { mbar_wait_(mbl[1], (unsigned)(phase1 & 1)); phase1++; }
            else             { mbar_wait_(mbl[0], (unsigned)(phase0 & 1)); phase0++; }
        }
    }
    cluster_sync_();   // safe teardown
}

// =====================================================================
// Phase 3: feats[t][j] = h[t] . W_out[j] + b_out[j]   (32 t-rows/block)
// =====================================================================
__global__ void __launch_bounds__(256) feats_kernel(
    const float* __restrict__ Wout, const float* __restrict__ bout)
{
    extern __shared__ float sm[];
    float* Ws = sm;                 // [32][513] padded
    float* hs = sm + KK_ * 513;     // [32][512]
    const int t0 = blockIdx.x * 32;
    const int tid = threadIdx.x;

    for (int i = tid; i < KK_ * HC_; i += 256) {
        int j = i >> 9, k = i & 511;
        Ws[j * 513 + k] = Wout[i];
    }
    const float* hflat = &g_h[t0][0];
    for (int i = tid; i < 32 * HC_; i += 256) hs[i] = hflat[i];
    __syncthreads();

    const int j = tid & 31;
    const int r0 = tid >> 5;
    const float bj = bout[j];
    for (int r = r0; r < 32; r += 8) {
        const float* hr = hs + r * HC_;
        const float* wr = Ws + j * 513;
        float s0 = 0.f, s1 = 0.f, s2 = 0.f, s3 = 0.f;
#pragma unroll 4
        for (int k = 0; k < HC_; k += 4) {
            s0 = fmaf(hr[k + 0], wr[k + 0], s0);
            s1 = fmaf(hr[k + 1], wr[k + 1], s1);
            s2 = fmaf(hr[k + 2], wr[k + 2], s2);
            s3 = fmaf(hr[k + 3], wr[k + 3], s3);
        }
        g_feats[t0 + r][j] = (s0 + s1) + (s2 + s3) + bj;
    }
}

// =====================================================================
// Phase 4: Viterbi. One block, 1024 threads: warp = tag j, lane = prev tag i.
// =====================================================================
#define VCHUNK 256

__global__ void __launch_bounds__(1024) viterbi_kernel(
    const float* __restrict__ trans, float* __restrict__ out, int out_size)
{
    extern __shared__ float smv[];
    float* transS = smv;                         // [32][32] transS[j][i] = trans[i][j]
    float* alpha  = transS + 1024;               // [2][32]
    float* fbuf   = alpha + 64;                  // [VCHUNK][32]
    unsigned char* ixs = (unsigned char*)(fbuf + VCHUNK * 32);  // [T-1][32]

    const int tid = threadIdx.x;
    const int i = tid & 31;     // previous tag (lane)
    const int j = tid >> 5;     // current tag (warp)

    transS[j * 32 + i] = trans[i * 32 + j];
    if (tid < 32) alpha[tid] = g_feats[0][tid];
    __syncthreads();
    const float tr = transS[j * 32 + i];
    const float* fflat = &g_feats[0][0];

    int p = 0;
    for (int t = 1; t < TT_; t++) {
        const int ci = (t - 1) & (VCHUNK - 1);
        if (ci == 0) {
            __syncthreads();
            const int base2 = t * 32;
            for (int u = tid; u < VCHUNK * 32 && base2 + u < TT_ * 32; u += 1024)
                fbuf[u] = fflat[base2 + u];
            __syncthreads();
        }
        float s = alpha[p * 32 + i] + tr;
        unsigned uu = __float_as_uint(s);
        uu = (uu & 0x80000000u) ? ~uu : (uu | 0x80000000u);
        unsigned best = __reduce_max_sync(0xffffffffu, uu);
        unsigned m = __ballot_sync(0xffffffffu, uu == best);
        int arg = __ffs(m) - 1;                     // lowest index on ties (matches argmax)
        float bs = __shfl_sync(0xffffffffu, s, arg);
        if (i == 0) {
            alpha[(p ^ 1) * 32 + j] = bs + fbuf[ci * 32 + j];
            ixs[(t - 1) * 32 + j] = (unsigned char)arg;
        }
        __syncthreads();
        p ^= 1;
    }

    if (tid < 32) {
        float s = alpha[p * 32 + i];
        unsigned uu = __float_as_uint(s);
        uu = (uu & 0x80000000u) ? ~uu : (uu | 0x80000000u);
        unsigned best = __reduce_max_sync(0xffffffffu, uu);
        unsigned m = __ballot_sync(0xffffffffu, uu == best);
        int arg = __ffs(m) - 1;
        float score = __shfl_sync(0xffffffffu, s, arg);
        if (i == 0) {
            if (out_size > TT_) out[TT_] = score;
            int cur = arg;
            out[TT_ - 1] = (float)cur;
            for (int t = TT_ - 2; t >= 0; t--) {
                cur = ixs[t * 32 + cur];
                out[t] = (float)cur;
            }
        }
    }
}

// =====================================================================
extern "C" void kernel_launch(void* const* d_in, const int* in_sizes, int n_in,
                              void* d_out, int out_size)
{
    const int*   sent  = (const int*)  d_in[0];
    const float* embed = (const float*)d_in[1];
    const float* WihF  = (const float*)d_in[2];
    const float* WhhF  = (const float*)d_in[3];
    const float* bihF  = (const float*)d_in[4];
    const float* bhhF  = (const float*)d_in[5];
    const float* WihB  = (const float*)d_in[6];
    const float* WhhB  = (const float*)d_in[7];
    const float* bihB  = (const float*)d_in[8];
    const float* bhhB  = (const float*)d_in[9];
    const float* h0    = (const float*)d_in[10];
    const float* c0    = (const float*)d_in[11];
    const float* Wout  = (const float*)d_in[12];
    const float* bout  = (const float*)d_in[13];
    const float* trans = (const float*)d_in[14];
    float* out = (float*)d_out;

    const int feats_smem = (KK_ * 513 + 32 * HC_) * 4;                        // ~131 KB
    const int vit_smem   = (1024 + 64 + VCHUNK * 32) * 4 + (TT_ - 1) * 32;    // ~168 KB
    cudaFuncSetAttribute(feats_kernel,   cudaFuncAttributeMaxDynamicSharedMemorySize, feats_smem);
    cudaFuncSetAttribute(viterbi_kernel, cudaFuncAttributeMaxDynamicSharedMemorySize, vit_smem);

    pre_gemm_kernel<<<dim3(16, 64, 2), 256>>>(sent, embed, WihF, bihF, bhhF, WihB, bihB, bhhB);
    // ncu alignment: shift -s 5 capture onto lstm_rec_kernel (launch idx 5)
    ncu_align_kernel<<<1, 32>>>();
    ncu_align_kernel<<<1, 32>>>();
    lstm_rec_kernel<<<16, 256>>>(WhhF, WhhB, h0, c0);
    feats_kernel<<<128, 256, feats_smem>>>(Wout, bout);
    viterbi_kernel<<<1, 1024, vit_smem>>>(trans, out, out_size);
}

// round 15
// speedup vs baseline: 2.4066x; 1.3238x over previous
#include <cuda_runtime.h>

// Problem dimensions (fixed by the reference)
#define TT_  4096   // sequence length T
#define EE_  256    // embed dim E
#define HH_  256    // per-direction hidden Hh
#define GG_  1024   // 4*Hh gate rows
#define KK_  32     // tags K
#define HC_  512    // concat hidden H

// ---------------- device scratch (no mallocs allowed) ----------------
__device__ float g_pre[2][TT_][GG_];   // input projections + biases, per direction (32 MB)
__device__ float g_h[TT_][HC_];        // concat hidden states (8 MB)
__device__ float g_feats[TT_][KK_];    // emission scores (512 KB)

// ---------------- packed fp32x2 helpers (SASS FFMA2) ----------------
__device__ __forceinline__ unsigned long long ffma2_(unsigned long long a,
                                                     unsigned long long b,
                                                     unsigned long long c) {
    unsigned long long d;
    asm("fma.rn.f32x2 %0, %1, %2, %3;" : "=l"(d) : "l"(a), "l"(b), "l"(c));
    return d;
}
__device__ __forceinline__ unsigned long long pack2_(float x) {
    unsigned long long d;
    asm("mov.b64 %0, {%1, %1};" : "=l"(d) : "f"(x));
    return d;
}
__device__ __forceinline__ float2 unpack2_(unsigned long long v) {
    float2 r;
    asm("mov.b64 {%0, %1}, %2;" : "=f"(r.x), "=f"(r.y) : "l"(v));
    return r;
}

// =====================================================================
// Phase 1: fused embedding gather + input projection GEMM (f32x2)
// =====================================================================
__global__ void __launch_bounds__(256) pre_gemm_kernel(
    const int* __restrict__ sent, const float* __restrict__ embed,
    const float* __restrict__ WihF, const float* __restrict__ bihF, const float* __restrict__ bhhF,
    const float* __restrict__ WihB, const float* __restrict__ bihB, const float* __restrict__ bhhB)
{
    const int dir = blockIdx.z;
    const float* __restrict__ Wih = dir ? WihB : WihF;
    const float* __restrict__ bih = dir ? bihB : bihF;
    const float* __restrict__ bhh = dir ? bhhB : bhhF;

    const int t0 = blockIdx.y * 64;
    const int j0 = blockIdx.x * 64;
    const int tid = threadIdx.x;

    __shared__ __align__(16) float As[32][68];
    __shared__ __align__(16) float Bs[32][68];
    __shared__ int ssent[64];

    if (tid < 64) ssent[tid] = sent[t0 + tid];
    __syncthreads();

    const int tl = tid >> 2;
    const int kq = (tid & 3) * 8;
    const int tm = tid & 15;
    const int tn = tid >> 4;

    unsigned long long acc2[4][2];
#pragma unroll
    for (int a = 0; a < 4; a++) { acc2[a][0] = 0ull; acc2[a][1] = 0ull; }

    for (int k0 = 0; k0 < EE_; k0 += 32) {
        const float4* ar = reinterpret_cast<const float4*>(embed + (size_t)ssent[tl] * EE_ + k0 + kq);
        float4 a0 = ar[0], a1 = ar[1];
        const float4* br = reinterpret_cast<const float4*>(Wih + (size_t)(j0 + tl) * EE_ + k0 + kq);
        float4 b0 = br[0], b1 = br[1];
        __syncthreads();
        As[kq + 0][tl] = a0.x; As[kq + 1][tl] = a0.y; As[kq + 2][tl] = a0.z; As[kq + 3][tl] = a0.w;
        As[kq + 4][tl] = a1.x; As[kq + 5][tl] = a1.y; As[kq + 6][tl] = a1.z; As[kq + 7][tl] = a1.w;
        Bs[kq + 0][tl] = b0.x; Bs[kq + 1][tl] = b0.y; Bs[kq + 2][tl] = b0.z; Bs[kq + 3][tl] = b0.w;
        Bs[kq + 4][tl] = b1.x; Bs[kq + 5][tl] = b1.y; Bs[kq + 6][tl] = b1.z; Bs[kq + 7][tl] = b1.w;
        __syncthreads();
#pragma unroll
        for (int kk = 0; kk < 32; kk++) {
            float4 av = *reinterpret_cast<const float4*>(&As[kk][tm * 4]);
            ulonglong2 bv = *reinterpret_cast<const ulonglong2*>(&Bs[kk][tn * 4]);
            unsigned long long sa0 = pack2_(av.x), sa1 = pack2_(av.y);
            unsigned long long sa2 = pack2_(av.z), sa3 = pack2_(av.w);
            acc2[0][0] = ffma2_(sa0, bv.x, acc2[0][0]); acc2[0][1] = ffma2_(sa0, bv.y, acc2[0][1]);
            acc2[1][0] = ffma2_(sa1, bv.x, acc2[1][0]); acc2[1][1] = ffma2_(sa1, bv.y, acc2[1][1]);
            acc2[2][0] = ffma2_(sa2, bv.x, acc2[2][0]); acc2[2][1] = ffma2_(sa2, bv.y, acc2[2][1]);
            acc2[3][0] = ffma2_(sa3, bv.x, acc2[3][0]); acc2[3][1] = ffma2_(sa3, bv.y, acc2[3][1]);
        }
    }

    float bias[4];
#pragma unroll
    for (int b = 0; b < 4; b++) bias[b] = bih[j0 + tn * 4 + b] + bhh[j0 + tn * 4 + b];

#pragma unroll
    for (int a = 0; a < 4; a++) {
        float2 p0 = unpack2_(acc2[a][0]);
        float2 p1 = unpack2_(acc2[a][1]);
        float4 v;
        v.x = p0.x + bias[0]; v.y = p0.y + bias[1];
        v.z = p1.x + bias[2]; v.w = p1.y + bias[3];
        *reinterpret_cast<float4*>(&g_pre[dir][t0 + tm * 4 + a][j0 + tn * 4]) = v;
    }
}

// ---------------- recurrence helpers ----------------
__device__ __forceinline__ float sigm_(float x) {
    return __fdividef(1.f, 1.f + __expf(-x));     // rcp.approx path
}
__device__ __forceinline__ float tanh_(float x) {
    return __fdividef(2.f, 1.f + __expf(-2.f * x)) - 1.f;
}
__device__ __forceinline__ void cluster_sync_() {
    asm volatile("barrier.cluster.arrive.aligned;" ::: "memory");
    asm volatile("barrier.cluster.wait.aligned;" ::: "memory");
}
__device__ __forceinline__ void mbar_wait_(unsigned mbar, unsigned parity) {
    unsigned done;
    asm volatile(
        "{\n\t.reg .pred p;\n\t"
        "mbarrier.try_wait.parity.acquire.cta.shared::cta.b64 p, [%1], %2, 0x989680;\n\t"
        "selp.b32 %0, 1, 0, p;\n\t}"
        : "=r"(done) : "r"(mbar), "r"(parity) : "memory");
    while (!done) {
        asm volatile(
            "{\n\t.reg .pred p;\n\t"
            "mbarrier.try_wait.parity.acquire.cta.shared::cta.b64 p, [%1], %2, 0x989680;\n\t"
            "selp.b32 %0, 1, 0, p;\n\t}"
            : "=r"(done) : "r"(mbar), "r"(parity) : "memory");
    }
}

// =====================================================================
// Phase 2: BiLSTM recurrence (R10 structure, 256 thr/CTA). 2 clusters x 8.
// tid = u*8 + sub, sub = g*2 + half. Per-thread single-destination send,
// hoisted mapa, acquire.cta waits.
// NEW (single change vs the 4768 baseline): only WARP 0 waits on the
// mbarrier; the other warps wait at __syncthreads(). Avoids 8 serialized
// TRYWAIT wakeups (~60 cyc each) at one barrier word per step; release
// chain is warp0-wakeup + BAR-release (~110 cyc total).
// =====================================================================
__global__ void __cluster_dims__(8, 1, 1) __launch_bounds__(256, 1) lstm_rec_kernel(
    const float* __restrict__ WhhF, const float* __restrict__ WhhB,
    const float* __restrict__ h0, const float* __restrict__ c0)
{
    __shared__ __align__(16) float hbuf[2][HH_];     // assembled h (all 8 chunks)
    __shared__ __align__(8) unsigned long long mbar[2];

    unsigned rank;
    asm("mov.u32 %0, %%cluster_ctarank;" : "=r"(rank));
    const int dir = blockIdx.x >> 3;
    const float* __restrict__ Whh = dir ? WhhB : WhhF;
    const float* __restrict__ pre = &g_pre[dir][0][0];

    const int tid  = threadIdx.x;
    const int u    = tid >> 3;          // hidden unit 0..31 within CTA
    const int sub  = tid & 7;           // also: destination CTA for the send
    const int g    = sub >> 1;          // gate 0..3 (i,f,g,o)
    const int half = sub & 1;           // column half
    const int gu   = (int)rank * 32 + u;
    const int grow = g * HH_ + gu;

    // weights into registers as packed f32x2
    unsigned long long w2[64];
    {
        const ulonglong2* wr = reinterpret_cast<const ulonglong2*>(
            Whh + (size_t)grow * HH_ + half * 128);
#pragma unroll
        for (int k = 0; k < 32; k++) {
            ulonglong2 v = wr[k];
            w2[2 * k] = v.x; w2[2 * k + 1] = v.y;
        }
    }

    // init state (all 8 threads of a unit track c redundantly & identically)
    if (tid < HH_) hbuf[0][tid] = h0[dir * HH_ + tid];
    float c = c0[dir * HH_ + gu];

    unsigned mbl[2];
    mbl[0] = (unsigned)__cvta_generic_to_shared(&mbar[0]);
    mbl[1] = (unsigned)__cvta_generic_to_shared(&mbar[1]);

    // hoisted remote addresses: this thread's destination slot in CTA 'sub'
    unsigned dstR[2], mbaR[2];
    {
        unsigned h0a = (unsigned)__cvta_generic_to_shared(&hbuf[0][0]) + ((unsigned)gu << 2);
        unsigned h1a = (unsigned)__cvta_generic_to_shared(&hbuf[1][0]) + ((unsigned)gu << 2);
        asm("mapa.shared::cluster.u32 %0, %1, %2;" : "=r"(dstR[0]) : "r"(h0a), "r"((unsigned)sub));
        asm("mapa.shared::cluster.u32 %0, %1, %2;" : "=r"(dstR[1]) : "r"(h1a), "r"((unsigned)sub));
        asm("mapa.shared::cluster.u32 %0, %1, %2;" : "=r"(mbaR[0]) : "r"(mbl[0]), "r"((unsigned)sub));
        asm("mapa.shared::cluster.u32 %0, %1, %2;" : "=r"(mbaR[1]) : "r"(mbl[1]), "r"((unsigned)sub));
    }

    if (tid == 0) {
        // 256 arrives per phase: 32 units x 8 source CTAs
        asm volatile("mbarrier.init.shared.b64 [%0], %1;" :: "r"(mbl[0]), "r"(256u) : "memory");
        asm volatile("mbarrier.init.shared.b64 [%0], %1;" :: "r"(mbl[1]), "r"(256u) : "memory");
    }
    __syncthreads();
    cluster_sync_();   // mbarrier init + hbuf[0] visible cluster-wide

    int phase0 = 0, phase1 = 0;
    const float gmul = (g == 2) ? 2.f : 1.f;   // tanh(x) = 2*sigm(2x)-1
    const int b0 = g & 1, b1 = g >> 1;

    // software prefetch of the input projection, 1 step ahead
    float prevN = pre[(size_t)(dir ? (TT_ - 1) : 0) * GG_ + grow];

    for (int s = 0; s < TT_; s++) {
        const int tt = dir ? (TT_ - 1 - s) : s;

        const float prev = prevN;
        if (s + 1 < TT_) {
            const int tn2 = dir ? (TT_ - 2 - s) : (s + 1);
            prevN = pre[(size_t)tn2 * GG_ + grow];   // issued early, consumed next step
        }

        const ulonglong2* h2 = reinterpret_cast<const ulonglong2*>(&hbuf[s & 1][half << 7]);
        unsigned long long a0 = 0ull, a1 = 0ull;
#pragma unroll
        for (int k = 0; k < 32; k++) {
            ulonglong2 hv = h2[k];
            a0 = ffma2_(w2[2 * k],     hv.x, a0);
            a1 = ffma2_(w2[2 * k + 1], hv.y, a1);
        }
        float2 p0 = unpack2_(a0), p1 = unpack2_(a1);
        float val = (p0.x + p0.y) + (p1.x + p1.y);
        if (!half) val += prev;
        val += __shfl_xor_sync(0xffffffffu, val, 1);   // full gate pre-activation (both halves)

        // own-gate nonlinearity
        float sg = sigm_(val * gmul);
        float A = (g == 2) ? (2.f * sg - 1.f) : sg;    // act of gate g

        // butterfly exchange: collect all 4 gate activations on all 8 threads
        float B = __shfl_xor_sync(0xffffffffu, A, 2);  // gate g^1
        float C = __shfl_xor_sync(0xffffffffu, A, 4);  // gate g^2
        float D = __shfl_xor_sync(0xffffffffu, B, 4);  // gate g^3
        // gate j = arr[j ^ g], arr = {A,B,C,D}
        float gi = b1 ? (b0 ? D : C) : (b0 ? B : A);   // gate 0 (i)
        float gf = b1 ? (b0 ? C : D) : (b0 ? A : B);   // gate 1 (f)
        float gg = b1 ? (b0 ? B : A) : (b0 ? D : C);   // gate 2 (g)
        float go = b1 ? (b0 ? A : B) : (b0 ? C : D);   // gate 3 (o)

        c = gf * c + gi * gg;
        float h = go * tanh_(c);

        if (s + 1 < TT_) {
            const int nb = (s + 1) & 1;
            // one remote store + one remote arrive per thread (dest = sub)
            asm volatile("st.shared::cluster.f32 [%0], %1;"
                         :: "r"(dstR[nb]), "f"(h) : "memory");
            asm volatile("mbarrier.arrive.shared::cluster.b64 _, [%0];"
                         :: "r"(mbaR[nb]) : "memory");
        }

        if (sub == 0) g_h[tt][dir * HH_ + gu] = h;   // off critical path

        if (s + 1 < TT_) {
            // only warp 0 sleeps on the mbarrier; everyone else parks at BAR
            if (tid < 32) {
                if ((s + 1) & 1) { mbar_wait_(mbl[1], (unsigned)(phase1 & 1)); phase1++; }
                else             { mbar_wait_(mbl[0], (unsigned)(phase0 & 1)); phase0++; }
            }
            __syncthreads();
        }
    }
    cluster_sync_();   // safe teardown
}

// =====================================================================
// Phase 3: feats[t][j] = h[t] . W_out[j] + b_out[j]   (32 t-rows/block)
// =====================================================================
__global__ void __launch_bounds__(256) feats_kernel(
    const float* __restrict__ Wout, const float* __restrict__ bout)
{
    extern __shared__ float sm[];
    float* Ws = sm;                 // [32][513] padded
    float* hs = sm + KK_ * 513;     // [32][512]
    const int t0 = blockIdx.x * 32;
    const int tid = threadIdx.x;

    for (int i = tid; i < KK_ * HC_; i += 256) {
        int j = i >> 9, k = i & 511;
        Ws[j * 513 + k] = Wout[i];
    }
    const float* hflat = &g_h[t0][0];
    for (int i = tid; i < 32 * HC_; i += 256) hs[i] = hflat[i];
    __syncthreads();

    const int j = tid & 31;
    const int r0 = tid >> 5;
    const float bj = bout[j];
    for (int r = r0; r < 32; r += 8) {
        const float* hr = hs + r * HC_;
        const float* wr = Ws + j * 513;
        float s0 = 0.f, s1 = 0.f, s2 = 0.f, s3 = 0.f;
#pragma unroll 4
        for (int k = 0; k < HC_; k += 4) {
            s0 = fmaf(hr[k + 0], wr[k + 0], s0);
            s1 = fmaf(hr[k + 1], wr[k + 1], s1);
            s2 = fmaf(hr[k + 2], wr[k + 2], s2);
            s3 = fmaf(hr[k + 3], wr[k + 3], s3);
        }
        g_feats[t0 + r][j] = (s0 + s1) + (s2 + s3) + bj;
    }
}

// =====================================================================
// Phase 4: Viterbi. One block, 1024 threads: warp = tag j, lane = prev tag i.
// =====================================================================
#define VCHUNK 256

__global__ void __launch_bounds__(1024) viterbi_kernel(
    const float* __restrict__ trans, float* __restrict__ out, int out_size)
{
    extern __shared__ float smv[];
    float* transS = smv;                         // [32][32] transS[j][i] = trans[i][j]
    float* alpha  = transS + 1024;               // [2][32]
    float* fbuf   = alpha + 64;                  // [VCHUNK][32]
    unsigned char* ixs = (unsigned char*)(fbuf + VCHUNK * 32);  // [T-1][32]

    const int tid = threadIdx.x;
    const int i = tid & 31;     // previous tag (lane)
    const int j = tid >> 5;     // current tag (warp)

    transS[j * 32 + i] = trans[i * 32 + j];
    if (tid < 32) alpha[tid] = g_feats[0][tid];
    __syncthreads();
    const float tr = transS[j * 32 + i];
    const float* fflat = &g_feats[0][0];

    int p = 0;
    for (int t = 1; t < TT_; t++) {
        const int ci = (t - 1) & (VCHUNK - 1);
        if (ci == 0) {
            __syncthreads();
            const int base2 = t * 32;
            for (int u = tid; u < VCHUNK * 32 && base2 + u < TT_ * 32; u += 1024)
                fbuf[u] = fflat[base2 + u];
            __syncthreads();
        }
        float s = alpha[p * 32 + i] + tr;
        unsigned uu = __float_as_uint(s);
        uu = (uu & 0x80000000u) ? ~uu : (uu | 0x80000000u);
        unsigned best = __reduce_max_sync(0xffffffffu, uu);
        unsigned m = __ballot_sync(0xffffffffu, uu == best);
        int arg = __ffs(m) - 1;                     // lowest index on ties (matches argmax)
        float bs = __shfl_sync(0xffffffffu, s, arg);
        if (i == 0) {
            alpha[(p ^ 1) * 32 + j] = bs + fbuf[ci * 32 + j];
            ixs[(t - 1) * 32 + j] = (unsigned char)arg;
        }
        __syncthreads();
        p ^= 1;
    }

    if (tid < 32) {
        float s = alpha[p * 32 + i];
        unsigned uu = __float_as_uint(s);
        uu = (uu & 0x80000000u) ? ~uu : (uu | 0x80000000u);
        unsigned best = __reduce_max_sync(0xffffffffu, uu);
        unsigned m = __ballot_sync(0xffffffffu, uu == best);
        int arg = __ffs(m) - 1;
        float score = __shfl_sync(0xffffffffu, s, arg);
        if (i == 0) {
            if (out_size > TT_) out[TT_] = score;
            int cur = arg;
            out[TT_ - 1] = (float)cur;
            for (int t = TT_ - 2; t >= 0; t--) {
                cur = ixs[t * 32 + cur];
                out[t] = (float)cur;
            }
        }
    }
}

// =====================================================================
extern "C" void kernel_launch(void* const* d_in, const int* in_sizes, int n_in,
                              void* d_out, int out_size)
{
    const int*   sent  = (const int*)  d_in[0];
    const float* embed = (const float*)d_in[1];
    const float* WihF  = (const float*)d_in[2];
    const float* WhhF  = (const float*)d_in[3];
    const float* bihF  = (const float*)d_in[4];
    const float* bhhF  = (const float*)d_in[5];
    const float* WihB  = (const float*)d_in[6];
    const float* WhhB  = (const float*)d_in[7];
    const float* bihB  = (const float*)d_in[8];
    const float* bhhB  = (const float*)d_in[9];
    const float* h0    = (const float*)d_in[10];
    const float* c0    = (const float*)d_in[11];
    const float* Wout  = (const float*)d_in[12];
    const float* bout  = (const float*)d_in[13];
    const float* trans = (const float*)d_in[14];
    float* out = (float*)d_out;

    const int feats_smem = (KK_ * 513 + 32 * HC_) * 4;                        // ~131 KB
    const int vit_smem   = (1024 + 64 + VCHUNK * 32) * 4 + (TT_ - 1) * 32;    // ~168 KB
    cudaFuncSetAttribute(feats_kernel,   cudaFuncAttributeMaxDynamicSharedMemorySize, feats_smem);
    cudaFuncSetAttribute(viterbi_kernel, cudaFuncAttributeMaxDynamicSharedMemorySize, vit_smem);

    pre_gemm_kernel<<<dim3(16, 64, 2), 256>>>(sent, embed, WihF, bihF, bhhF, WihB, bihB, bhhB);
    lstm_rec_kernel<<<16, 256>>>(WhhF, WhhB, h0, c0);
    feats_kernel<<<128, 256, feats_smem>>>(Wout, bout);
    viterbi_kernel<<<1, 1024, vit_smem>>>(trans, out, out_size);
}

// round 17
// speedup vs baseline: 3.0046x; 1.2485x over previous
#include <cuda_runtime.h>

// Problem dimensions (fixed by the reference)
#define TT_  4096   // sequence length T
#define EE_  256    // embed dim E
#define HH_  256    // per-direction hidden Hh
#define GG_  1024   // 4*Hh gate rows
#define KK_  32     // tags K
#define HC_  512    // concat hidden H

// ---------------- device scratch (no mallocs allowed) ----------------
__device__ float g_pre[2][TT_][GG_];   // input projections + biases, per direction (32 MB)
__device__ float g_h[TT_][HC_];        // concat hidden states (8 MB)
__device__ float g_feats[TT_][KK_];    // emission scores (512 KB)

// ---------------- packed fp32x2 helpers (SASS FFMA2) ----------------
__device__ __forceinline__ unsigned long long ffma2_(unsigned long long a,
                                                     unsigned long long b,
                                                     unsigned long long c) {
    unsigned long long d;
    asm("fma.rn.f32x2 %0, %1, %2, %3;" : "=l"(d) : "l"(a), "l"(b), "l"(c));
    return d;
}
__device__ __forceinline__ unsigned long long pack2_(float x) {
    unsigned long long d;
    asm("mov.b64 %0, {%1, %1};" : "=l"(d) : "f"(x));
    return d;
}
__device__ __forceinline__ float2 unpack2_(unsigned long long v) {
    float2 r;
    asm("mov.b64 {%0, %1}, %2;" : "=f"(r.x), "=f"(r.y) : "l"(v));
    return r;
}

// =====================================================================
// Phase 1: fused embedding gather + input projection GEMM (f32x2)
// =====================================================================
__global__ void __launch_bounds__(256) pre_gemm_kernel(
    const int* __restrict__ sent, const float* __restrict__ embed,
    const float* __restrict__ WihF, const float* __restrict__ bihF, const float* __restrict__ bhhF,
    const float* __restrict__ WihB, const float* __restrict__ bihB, const float* __restrict__ bhhB)
{
    const int dir = blockIdx.z;
    const float* __restrict__ Wih = dir ? WihB : WihF;
    const float* __restrict__ bih = dir ? bihB : bihF;
    const float* __restrict__ bhh = dir ? bhhB : bhhF;

    const int t0 = blockIdx.y * 64;
    const int j0 = blockIdx.x * 64;
    const int tid = threadIdx.x;

    __shared__ __align__(16) float As[32][68];
    __shared__ __align__(16) float Bs[32][68];
    __shared__ int ssent[64];

    if (tid < 64) ssent[tid] = sent[t0 + tid];
    __syncthreads();

    const int tl = tid >> 2;
    const int kq = (tid & 3) * 8;
    const int tm = tid & 15;
    const int tn = tid >> 4;

    unsigned long long acc2[4][2];
#pragma unroll
    for (int a = 0; a < 4; a++) { acc2[a][0] = 0ull; acc2[a][1] = 0ull; }

    for (int k0 = 0; k0 < EE_; k0 += 32) {
        const float4* ar = reinterpret_cast<const float4*>(embed + (size_t)ssent[tl] * EE_ + k0 + kq);
        float4 a0 = ar[0], a1 = ar[1];
        const float4* br = reinterpret_cast<const float4*>(Wih + (size_t)(j0 + tl) * EE_ + k0 + kq);
        float4 b0 = br[0], b1 = br[1];
        __syncthreads();
        As[kq + 0][tl] = a0.x; As[kq + 1][tl] = a0.y; As[kq + 2][tl] = a0.z; As[kq + 3][tl] = a0.w;
        As[kq + 4][tl] = a1.x; As[kq + 5][tl] = a1.y; As[kq + 6][tl] = a1.z; As[kq + 7][tl] = a1.w;
        Bs[kq + 0][tl] = b0.x; Bs[kq + 1][tl] = b0.y; Bs[kq + 2][tl] = b0.z; Bs[kq + 3][tl] = b0.w;
        Bs[kq + 4][tl] = b1.x; Bs[kq + 5][tl] = b1.y; Bs[kq + 6][tl] = b1.z; Bs[kq + 7][tl] = b1.w;
        __syncthreads();
#pragma unroll
        for (int kk = 0; kk < 32; kk++) {
            float4 av = *reinterpret_cast<const float4*>(&As[kk][tm * 4]);
            ulonglong2 bv = *reinterpret_cast<const ulonglong2*>(&Bs[kk][tn * 4]);
            unsigned long long sa0 = pack2_(av.x), sa1 = pack2_(av.y);
            unsigned long long sa2 = pack2_(av.z), sa3 = pack2_(av.w);
            acc2[0][0] = ffma2_(sa0, bv.x, acc2[0][0]); acc2[0][1] = ffma2_(sa0, bv.y, acc2[0][1]);
            acc2[1][0] = ffma2_(sa1, bv.x, acc2[1][0]); acc2[1][1] = ffma2_(sa1, bv.y, acc2[1][1]);
            acc2[2][0] = ffma2_(sa2, bv.x, acc2[2][0]); acc2[2][1] = ffma2_(sa2, bv.y, acc2[2][1]);
            acc2[3][0] = ffma2_(sa3, bv.x, acc2[3][0]); acc2[3][1] = ffma2_(sa3, bv.y, acc2[3][1]);
        }
    }

    float bias[4];
#pragma unroll
    for (int b = 0; b < 4; b++) bias[b] = bih[j0 + tn * 4 + b] + bhh[j0 + tn * 4 + b];

#pragma unroll
    for (int a = 0; a < 4; a++) {
        float2 p0 = unpack2_(acc2[a][0]);
        float2 p1 = unpack2_(acc2[a][1]);
        float4 v;
        v.x = p0.x + bias[0]; v.y = p0.y + bias[1];
        v.z = p1.x + bias[2]; v.w = p1.y + bias[3];
        *reinterpret_cast<float4*>(&g_pre[dir][t0 + tm * 4 + a][j0 + tn * 4]) = v;
    }
}

// ---------------- recurrence helpers ----------------
__device__ __forceinline__ float sigm_(float x) {
    return __fdividef(1.f, 1.f + __expf(-x));     // rcp.approx path
}
__device__ __forceinline__ float tanh_(float x) {
    return __fdividef(2.f, 1.f + __expf(-2.f * x)) - 1.f;
}
__device__ __forceinline__ void cluster_sync_() {
    asm volatile("barrier.cluster.arrive.aligned;" ::: "memory");
    asm volatile("barrier.cluster.wait.aligned;" ::: "memory");
}
__device__ __forceinline__ void mbar_wait_(unsigned mbar, unsigned parity) {
    unsigned done;
    asm volatile(
        "{\n\t.reg .pred p;\n\t"
        "mbarrier.try_wait.parity.acquire.cta.shared::cta.b64 p, [%1], %2, 0x989680;\n\t"
        "selp.b32 %0, 1, 0, p;\n\t}"
        : "=r"(done) : "r"(mbar), "r"(parity) : "memory");
    while (!done) {
        asm volatile(
            "{\n\t.reg .pred p;\n\t"
            "mbarrier.try_wait.parity.acquire.cta.shared::cta.b64 p, [%1], %2, 0x989680;\n\t"
            "selp.b32 %0, 1, 0, p;\n\t}"
            : "=r"(done) : "r"(mbar), "r"(parity) : "memory");
    }
}

// =====================================================================
// Phase 2: BiLSTM recurrence. 2 clusters of 8 CTAs, 256 thr/CTA.
// TRANSPOSED layout: warp w = (gate g = w>>1, half = w&1), lane u = unit.
// Per step: (1) all warps dot -> part[w][u]; (2) warps 0..3 gate sum +
// nonlinearity -> act[g][u]; (3) warp 0: c/h -> hOut; (4) each warp sends
// hOut as ONE coalesced 128B remote store to dest CTA w + 1 arrive.
// Destination incoming traffic: 8 contiguous stores + 8 arrives per step
// (was 64 scattered packets + 32 arrives). Barrier count 8/phase
// (FIXED: was mistakenly 64 in R15 -> deadlock).
// =====================================================================
__global__ void __cluster_dims__(8, 1, 1) __launch_bounds__(256, 1) lstm_rec_kernel(
    const float* __restrict__ WhhF, const float* __restrict__ WhhB,
    const float* __restrict__ h0, const float* __restrict__ c0)
{
    __shared__ __align__(16) float hbuf[2][HH_];     // assembled h (all 8 chunks)
    __shared__ __align__(16) float part[8][33];      // dot partials (padded)
    __shared__ __align__(16) float act[4][33];       // gate activations (padded)
    __shared__ __align__(16) float hOut[32];         // this CTA's new h chunk
    __shared__ __align__(8) unsigned long long mbar[2];

    unsigned rank;
    asm("mov.u32 %0, %%cluster_ctarank;" : "=r"(rank));
    const int dir = blockIdx.x >> 3;
    const float* __restrict__ Whh = dir ? WhhB : WhhF;
    const float* __restrict__ pre = &g_pre[dir][0][0];

    const int tid  = threadIdx.x;
    const int w    = tid >> 5;          // warp 0..7 = (gate, half); also dest CTA
    const int u    = tid & 31;          // hidden unit within CTA
    const int g    = w >> 1;            // gate of this warp's dot rows
    const int half = w & 1;             // column half
    const int gu   = (int)rank * 32 + u;
    const int grow = g * HH_ + gu;      // dot row for stage 1
    const int grow2 = w * HH_ + gu;     // stage-2 row (warps 0..3: gate w)

    // weights (row grow, this half) into registers as packed f32x2
    unsigned long long w2[64];
    {
        const ulonglong2* wr = reinterpret_cast<const ulonglong2*>(
            Whh + (size_t)grow * HH_ + half * 128);
#pragma unroll
        for (int k = 0; k < 32; k++) {
            ulonglong2 v = wr[k];
            w2[2 * k] = v.x; w2[2 * k + 1] = v.y;
        }
    }

    if (tid < HH_) hbuf[0][tid] = h0[dir * HH_ + tid];
    float c = c0[dir * HH_ + gu];       // used by warp 0 only

    unsigned mbl[2];
    mbl[0] = (unsigned)__cvta_generic_to_shared(&mbar[0]);
    mbl[1] = (unsigned)__cvta_generic_to_shared(&mbar[1]);

    // hoisted remote addresses: warp w writes hOut -> CTA w, slot gu
    unsigned dstR[2], mbaR[2];
    {
        unsigned h0a = (unsigned)__cvta_generic_to_shared(&hbuf[0][0]) + ((unsigned)gu << 2);
        unsigned h1a = (unsigned)__cvta_generic_to_shared(&hbuf[1][0]) + ((unsigned)gu << 2);
        asm("mapa.shared::cluster.u32 %0, %1, %2;" : "=r"(dstR[0]) : "r"(h0a), "r"((unsigned)w));
        asm("mapa.shared::cluster.u32 %0, %1, %2;" : "=r"(dstR[1]) : "r"(h1a), "r"((unsigned)w));
        asm("mapa.shared::cluster.u32 %0, %1, %2;" : "=r"(mbaR[0]) : "r"(mbl[0]), "r"((unsigned)w));
        asm("mapa.shared::cluster.u32 %0, %1, %2;" : "=r"(mbaR[1]) : "r"(mbl[1]), "r"((unsigned)w));
    }

    if (tid == 0) {
        // 8 arrives per phase: one per source CTA (its warp 'ourRank', lane 0)
        asm volatile("mbarrier.init.shared.b64 [%0], %1;" :: "r"(mbl[0]), "r"(8u) : "memory");
        asm volatile("mbarrier.init.shared.b64 [%0], %1;" :: "r"(mbl[1]), "r"(8u) : "memory");
    }
    __syncthreads();
    cluster_sync_();   // mbarrier init + hbuf[0] visible cluster-wide

    int phase0 = 0, phase1 = 0;
    const float gmul2 = (w == 2) ? 2.f : 1.f;   // stage-2: tanh via 2*sigm(2x)-1

    // software prefetch of the input projection (stage-2 threads), 1 step ahead
    float prevN = (tid < 128) ? pre[(size_t)(dir ? (TT_ - 1) : 0) * GG_ + grow2] : 0.f;

    for (int s = 0; s < TT_; s++) {
        const int tt = dir ? (TT_ - 1 - s) : s;

        const float prev = prevN;
        if (tid < 128 && s + 1 < TT_) {
            const int tn2 = dir ? (TT_ - 2 - s) : (s + 1);
            prevN = pre[(size_t)tn2 * GG_ + grow2];   // issued early, consumed next step
        }

        // ---- stage 1: half-row dot (all warps) ----
        const ulonglong2* h2 = reinterpret_cast<const ulonglong2*>(&hbuf[s & 1][half << 7]);
        unsigned long long a0 = 0ull, a1 = 0ull;
#pragma unroll
        for (int k = 0; k < 32; k++) {
            ulonglong2 hv = h2[k];
            a0 = ffma2_(w2[2 * k],     hv.x, a0);
            a1 = ffma2_(w2[2 * k + 1], hv.y, a1);
        }
        float2 p0 = unpack2_(a0), p1 = unpack2_(a1);
        part[w][u] = (p0.x + p0.y) + (p1.x + p1.y);
        __syncthreads();

        // ---- stage 2: gate pre-activation + nonlinearity (warps 0..3) ----
        if (tid < 128) {
            float G = part[2 * w][u] + part[2 * w + 1][u] + prev;
            float sg = sigm_(G * gmul2);
            act[w][u] = (w == 2) ? (2.f * sg - 1.f) : sg;
        }
        __syncthreads();

        // ---- stage 3: c/h update (warp 0) ----
        if (w == 0) {
            float gi = act[0][u], gf = act[1][u], gg = act[2][u], go = act[3][u];
            c = gf * c + gi * gg;
            float h = go * tanh_(c);
            hOut[u] = h;
            g_h[tt][dir * HH_ + gu] = h;   // coalesced 128B global store
        }
        __syncthreads();

        // ---- stage 4: coalesced broadcast (all warps, one dest each) ----
        if (s + 1 < TT_) {
            const int nb = (s + 1) & 1;
            float hv = hOut[u];            // conflict-free LDS
            asm volatile("st.shared::cluster.f32 [%0], %1;"
                         :: "r"(dstR[nb]), "f"(hv) : "memory");
            __syncwarp(0xffffffffu);
            if (u == 0) {
                asm volatile("mbarrier.arrive.shared::cluster.b64 _, [%0];"
                             :: "r"(mbaR[nb]) : "memory");
            }
            if (nb) { mbar_wait_(mbl[1], (unsigned)(phase1 & 1)); phase1++; }
            else    { mbar_wait_(mbl[0], (unsigned)(phase0 & 1)); phase0++; }
        }
    }
    cluster_sync_();   // safe teardown
}

// =====================================================================
// Phase 3: feats[t][j] = h[t] . W_out[j] + b_out[j]   (32 t-rows/block)
// =====================================================================
__global__ void __launch_bounds__(256) feats_kernel(
    const float* __restrict__ Wout, const float* __restrict__ bout)
{
    extern __shared__ float sm[];
    float* Ws = sm;                 // [32][513] padded
    float* hs = sm + KK_ * 513;     // [32][512]
    const int t0 = blockIdx.x * 32;
    const int tid = threadIdx.x;

    for (int i = tid; i < KK_ * HC_; i += 256) {
        int j = i >> 9, k = i & 511;
        Ws[j * 513 + k] = Wout[i];
    }
    const float* hflat = &g_h[t0][0];
    for (int i = tid; i < 32 * HC_; i += 256) hs[i] = hflat[i];
    __syncthreads();

    const int j = tid & 31;
    const int r0 = tid >> 5;
    const float bj = bout[j];
    for (int r = r0; r < 32; r += 8) {
        const float* hr = hs + r * HC_;
        const float* wr = Ws + j * 513;
        float s0 = 0.f, s1 = 0.f, s2 = 0.f, s3 = 0.f;
#pragma unroll 4
        for (int k = 0; k < HC_; k += 4) {
            s0 = fmaf(hr[k + 0], wr[k + 0], s0);
            s1 = fmaf(hr[k + 1], wr[k + 1], s1);
            s2 = fmaf(hr[k + 2], wr[k + 2], s2);
            s3 = fmaf(hr[k + 3], wr[k + 3], s3);
        }
        g_feats[t0 + r][j] = (s0 + s1) + (s2 + s3) + bj;
    }
}

// =====================================================================
// Phase 4: Viterbi. One block, 1024 threads: warp = tag j, lane = prev tag i.
// =====================================================================
#define VCHUNK 256

__global__ void __launch_bounds__(1024) viterbi_kernel(
    const float* __restrict__ trans, float* __restrict__ out, int out_size)
{
    extern __shared__ float smv[];
    float* transS = smv;                         // [32][32] transS[j][i] = trans[i][j]
    float* alpha  = transS + 1024;               // [2][32]
    float* fbuf   = alpha + 64;                  // [VCHUNK][32]
    unsigned char* ixs = (unsigned char*)(fbuf + VCHUNK * 32);  // [T-1][32]

    const int tid = threadIdx.x;
    const int i = tid & 31;     // previous tag (lane)
    const int j = tid >> 5;     // current tag (warp)

    transS[j * 32 + i] = trans[i * 32 + j];
    if (tid < 32) alpha[tid] = g_feats[0][tid];
    __syncthreads();
    const float tr = transS[j * 32 + i];
    const float* fflat = &g_feats[0][0];

    int p = 0;
    for (int t = 1; t < TT_; t++) {
        const int ci = (t - 1) & (VCHUNK - 1);
        if (ci == 0) {
            __syncthreads();
            const int base2 = t * 32;
            for (int u = tid; u < VCHUNK * 32 && base2 + u < TT_ * 32; u += 1024)
                fbuf[u] = fflat[base2 + u];
            __syncthreads();
        }
        float s = alpha[p * 32 + i] + tr;
        unsigned uu = __float_as_uint(s);
        uu = (uu & 0x80000000u) ? ~uu : (uu | 0x80000000u);
        unsigned best = __reduce_max_sync(0xffffffffu, uu);
        unsigned m = __ballot_sync(0xffffffffu, uu == best);
        int arg = __ffs(m) - 1;                     // lowest index on ties (matches argmax)
        float bs = __shfl_sync(0xffffffffu, s, arg);
        if (i == 0) {
            alpha[(p ^ 1) * 32 + j] = bs + fbuf[ci * 32 + j];
            ixs[(t - 1) * 32 + j] = (unsigned char)arg;
        }
        __syncthreads();
        p ^= 1;
    }

    if (tid < 32) {
        float s = alpha[p * 32 + i];
        unsigned uu = __float_as_uint(s);
        uu = (uu & 0x80000000u) ? ~uu : (uu | 0x80000000u);
        unsigned best = __reduce_max_sync(0xffffffffu, uu);
        unsigned m = __ballot_sync(0xffffffffu, uu == best);
        int arg = __ffs(m) - 1;
        float score = __shfl_sync(0xffffffffu, s, arg);
        if (i == 0) {
            if (out_size > TT_) out[TT_] = score;
            int cur = arg;
            out[TT_ - 1] = (float)cur;
            for (int t = TT_ - 2; t >= 0; t--) {
                cur = ixs[t * 32 + cur];
                out[t] = (float)cur;
            }
        }
    }
}

// =====================================================================
extern "C" void kernel_launch(void* const* d_in, const int* in_sizes, int n_in,
                              void* d_out, int out_size)
{
    const int*   sent  = (const int*)  d_in[0];
    const float* embed = (const float*)d_in[1];
    const float* WihF  = (const float*)d_in[2];
    const float* WhhF  = (const float*)d_in[3];
    const float* bihF  = (const float*)d_in[4];
    const float* bhhF  = (const float*)d_in[5];
    const float* WihB  = (const float*)d_in[6];
    const float* WhhB  = (const float*)d_in[7];
    const float* bihB  = (const float*)d_in[8];
    const float* bhhB  = (const float*)d_in[9];
    const float* h0    = (const float*)d_in[10];
    const float* c0    = (const float*)d_in[11];
    const float* Wout  = (const float*)d_in[12];
    const float* bout  = (const float*)d_in[13];
    const float* trans = (const float*)d_in[14];
    float* out = (float*)d_out;

    const int feats_smem = (KK_ * 513 + 32 * HC_) * 4;                        // ~131 KB
    const int vit_smem   = (1024 + 64 + VCHUNK * 32) * 4 + (TT_ - 1) * 32;    // ~168 KB
    cudaFuncSetAttribute(feats_kernel,   cudaFuncAttributeMaxDynamicSharedMemorySize, feats_smem);
    cudaFuncSetAttribute(viterbi_kernel, cudaFuncAttributeMaxDynamicSharedMemorySize, vit_smem);

    pre_gemm_kernel<<<dim3(16, 64, 2), 256>>>(sent, embed, WihF, bihF, bhhF, WihB, bihB, bhhB);
    lstm_rec_kernel<<<16, 256>>>(WhhF, WhhB, h0, c0);
    feats_kernel<<<128, 256, feats_smem>>>(Wout, bout);
    viterbi_kernel<<<1, 1024, vit_smem>>>(trans, out, out_size);
}